// round 3
// baseline (speedup 1.0000x reference)
#include <cuda_runtime.h>

#define GHM_BINS 10
#define GHM_BLOCK 256
#define GHM_GRID (148 * 8)

// Global accumulators (allocation-free scratch). Zero at module load; the
// last block resets them after finalizing, so every launch starts clean.
__device__ float g_ghm_counts[GHM_BINS];
__device__ float g_ghm_sums[GHM_BINS];
__device__ unsigned int g_ghm_ticket;

__device__ __forceinline__ void ghm_accum_elem(float p, float t, float w,
                                               float2* hist_col /* &hist[0][tid], stride GHM_BLOCK */) {
    // e = exp(-|p|)
    float ap = fabsf(p);
    float e  = __expf(-ap);              // MUFU.EX2 path
    float d  = 1.0f + e;
    float lp = __logf(d);                // log1p(exp(-|p|)); MUFU.LG2
    // stable BCE-with-logits
    float bce = fmaxf(p, 0.0f) - p * t + lp;
    // sigmoid(p) from same e: p>=0 -> 1/(1+e), else e/(1+e) = 1 - 1/(1+e)
    float u = __fdividef(1.0f, d);       // MUFU.RCP
    float s = (p >= 0.0f) ? u : (1.0f - u);
    float g10 = fabsf(s - t) * 10.0f;    // g in [0,1] -> g10 in [0,10]
    int idx = (int)g10;                  // floor (g10 >= 0)
    idx = min(idx, GHM_BINS - 1);        // clip top edge
    float vf = (w > 0.0f) ? 1.0f : 0.0f;
    float2 h = hist_col[idx * GHM_BLOCK];
    h.x += vf;
    h.y = fmaf(vf, bce, h.y);
    hist_col[idx * GHM_BLOCK] = h;
}

__global__ __launch_bounds__(GHM_BLOCK)
void ghm_main_kernel(const float4* __restrict__ pred4,
                     const float4* __restrict__ targ4,
                     const float4* __restrict__ lw4,
                     const float* __restrict__ pred,
                     const float* __restrict__ targ,
                     const float* __restrict__ lw,
                     long long nvec, long long ntotal,
                     float* __restrict__ out) {
    // Thread-private histogram stripes: hist[bin][tid] as {count, bce_sum}.
    // Address = (bin*GHM_BLOCK + tid)*8 bytes -> conflict-free LDS.64/STS.64.
    __shared__ float2 hist[GHM_BINS][GHM_BLOCK];
    __shared__ bool s_is_last;

    const int tid = threadIdx.x;
#pragma unroll
    for (int b = 0; b < GHM_BINS; b++) hist[b][tid] = make_float2(0.0f, 0.0f);
    __syncthreads();

    float2* hist_col = &hist[0][tid];

    const long long T = (long long)gridDim.x * (long long)blockDim.x;
    const long long gid = (long long)blockIdx.x * blockDim.x + tid;
    const long long nvec2 = nvec >> 1;   // pairs of float4

    // Main loop: 2 consecutive float4 per array per thread per iter.
    // 6 front-batched LDG.128 -> 2x in-flight bytes per warp vs unroll-1.
    for (long long i = gid; i < nvec2; i += T) {
        long long j = 2 * i;
        float4 p0 = __ldcs(&pred4[j]);
        float4 p1 = __ldcs(&pred4[j + 1]);
        float4 t0 = __ldcs(&targ4[j]);
        float4 t1 = __ldcs(&targ4[j + 1]);
        float4 w0 = __ldcs(&lw4[j]);
        float4 w1 = __ldcs(&lw4[j + 1]);
        ghm_accum_elem(p0.x, t0.x, w0.x, hist_col);
        ghm_accum_elem(p0.y, t0.y, w0.y, hist_col);
        ghm_accum_elem(p0.z, t0.z, w0.z, hist_col);
        ghm_accum_elem(p0.w, t0.w, w0.w, hist_col);
        ghm_accum_elem(p1.x, t1.x, w1.x, hist_col);
        ghm_accum_elem(p1.y, t1.y, w1.y, hist_col);
        ghm_accum_elem(p1.z, t1.z, w1.z, hist_col);
        ghm_accum_elem(p1.w, t1.w, w1.w, hist_col);
    }

    // Leftover float4 (when nvec is odd) — first threads of block 0.
    long long done4 = nvec2 * 2;
    if (blockIdx.x == 0 && done4 + tid < nvec) {
        long long j = done4 + tid;
        float4 p = __ldcs(&pred4[j]);
        float4 t = __ldcs(&targ4[j]);
        float4 w = __ldcs(&lw4[j]);
        ghm_accum_elem(p.x, t.x, w.x, hist_col);
        ghm_accum_elem(p.y, t.y, w.y, hist_col);
        ghm_accum_elem(p.z, t.z, w.z, hist_col);
        ghm_accum_elem(p.w, t.w, w.w, hist_col);
    }

    // Scalar tail (ntotal not divisible by 4) — first threads of block 0.
    long long tail_base = nvec * 4;
    long long rem = ntotal - tail_base;
    if (blockIdx.x == 0 && (long long)tid < rem) {
        long long j = tail_base + tid;
        ghm_accum_elem(__ldcs(&pred[j]), __ldcs(&targ[j]), __ldcs(&lw[j]), hist_col);
    }

    __syncthreads();

    // Block tree reduction over the thread dimension for each bin.
    for (int off = GHM_BLOCK / 2; off > 0; off >>= 1) {
        if (tid < off) {
#pragma unroll
            for (int b = 0; b < GHM_BINS; b++) {
                float2 a = hist[b][tid];
                float2 c = hist[b][tid + off];
                hist[b][tid] = make_float2(a.x + c.x, a.y + c.y);
            }
        }
        __syncthreads();
    }

    if (tid < GHM_BINS) {
        atomicAdd(&g_ghm_counts[tid], hist[tid][0].x);
        atomicAdd(&g_ghm_sums[tid],   hist[tid][0].y);
    }

    // Last-block finalize (threadFenceReduction pattern).
    __threadfence();
    if (tid == 0) {
        unsigned int t = atomicAdd(&g_ghm_ticket, 1u);
        s_is_last = (t == gridDim.x - 1);
    }
    __syncthreads();

    if (s_is_last && tid == 0) {
        // loss = (sum over nonempty bins of S_b / count_b) / max(n, 1);
        // tot cancels between w_per_bin = tot/count and the final /tot.
        float n = 0.0f;
        float acc = 0.0f;
#pragma unroll
        for (int b = 0; b < GHM_BINS; b++) {
            float c = g_ghm_counts[b];
            if (c > 0.0f) {
                n += 1.0f;
                acc += g_ghm_sums[b] / c;
            }
        }
        out[0] = acc / fmaxf(n, 1.0f);

        // Reset globals for the next (graph-replayed) launch.
#pragma unroll
        for (int b = 0; b < GHM_BINS; b++) {
            g_ghm_counts[b] = 0.0f;
            g_ghm_sums[b]   = 0.0f;
        }
        __threadfence();
        g_ghm_ticket = 0u;
    }
}

extern "C" void kernel_launch(void* const* d_in, const int* in_sizes, int n_in,
                              void* d_out, int out_size) {
    const float* pred = (const float*)d_in[0];
    const float* targ = (const float*)d_in[1];
    const float* lw   = (const float*)d_in[2];
    float* out = (float*)d_out;

    long long ntotal = (long long)in_sizes[0];
    long long nvec = ntotal / 4;

    ghm_main_kernel<<<GHM_GRID, GHM_BLOCK>>>(
        (const float4*)pred, (const float4*)targ, (const float4*)lw,
        pred, targ, lw, nvec, ntotal, out);
    (void)n_in; (void)out_size;
}

// round 4
// speedup vs baseline: 1.0973x; 1.0973x over previous
#include <cuda_runtime.h>

#define GHM_BINS 10
#define GHM_BLOCK 256
#define GHM_GRID (148 * 8)

// Global accumulators (allocation-free scratch). Zero at module load; the
// last block resets them after finalizing, so every launch starts clean.
__device__ float g_ghm_counts[GHM_BINS];
__device__ float g_ghm_sums[GHM_BINS];
__device__ unsigned int g_ghm_ticket;

__device__ __forceinline__ void ghm_accum_elem(float p, float t, float w,
                                               float2* hist_col /* &hist[0][tid], stride GHM_BLOCK */) {
    // e = exp(-|p|)
    float ap = fabsf(p);
    float e  = __expf(-ap);              // MUFU.EX2 path
    float d  = 1.0f + e;
    float lp = __logf(d);                // log1p(exp(-|p|)); MUFU.LG2
    // stable BCE-with-logits
    float bce = fmaxf(p, 0.0f) - p * t + lp;
    // sigmoid(p) from same e: p>=0 -> 1/(1+e), else e/(1+e) = 1 - 1/(1+e)
    float u = __fdividef(1.0f, d);       // MUFU.RCP
    float s = (p >= 0.0f) ? u : (1.0f - u);
    float g10 = fabsf(s - t) * 10.0f;    // g in [0,1] -> g10 in [0,10]
    int idx = (int)g10;                  // floor (g10 >= 0)
    idx = min(idx, GHM_BINS - 1);        // clip top edge
    float vf = (w > 0.0f) ? 1.0f : 0.0f;
    float2 h = hist_col[idx * GHM_BLOCK];
    h.x += vf;
    h.y = fmaf(vf, bce, h.y);
    hist_col[idx * GHM_BLOCK] = h;
}

__device__ __forceinline__ void ghm_accum_vec4(float4 p, float4 t, float4 w,
                                               float2* hist_col) {
    ghm_accum_elem(p.x, t.x, w.x, hist_col);
    ghm_accum_elem(p.y, t.y, w.y, hist_col);
    ghm_accum_elem(p.z, t.z, w.z, hist_col);
    ghm_accum_elem(p.w, t.w, w.w, hist_col);
}

__global__ __launch_bounds__(GHM_BLOCK)
void ghm_main_kernel(const float4* __restrict__ pred4,
                     const float4* __restrict__ targ4,
                     const float4* __restrict__ lw4,
                     const float* __restrict__ pred,
                     const float* __restrict__ targ,
                     const float* __restrict__ lw,
                     long long nvec, long long ntotal,
                     float* __restrict__ out) {
    // Thread-private histogram stripes: hist[bin][tid] as {count, bce_sum}.
    // Address = (bin*GHM_BLOCK + tid)*8 bytes -> conflict-free LDS.64/STS.64.
    __shared__ float2 hist[GHM_BINS][GHM_BLOCK];
    __shared__ bool s_is_last;

    const int tid = threadIdx.x;
#pragma unroll
    for (int b = 0; b < GHM_BINS; b++) hist[b][tid] = make_float2(0.0f, 0.0f);
    __syncthreads();

    float2* hist_col = &hist[0][tid];

    const long long T = (long long)gridDim.x * GHM_BLOCK;
    const long long gid = (long long)blockIdx.x * GHM_BLOCK + tid;
    // Per grid pass: 2T float4s. Block b owns two coalesced tiles:
    //   [s + b*2B + tid]  and  [s + b*2B + B + tid]
    // -> every LDG.128 covers exactly 4 consecutive 128B lines per warp.
    const long long pass = 2 * T;
    const long long nmain = (nvec / pass) * pass;
    const long long blk_base = (long long)blockIdx.x * (2 * GHM_BLOCK) + tid;

    for (long long s = 0; s < nmain; s += pass) {
        long long i0 = s + blk_base;
        long long i1 = i0 + GHM_BLOCK;
        float4 p0 = __ldcs(&pred4[i0]);
        float4 p1 = __ldcs(&pred4[i1]);
        float4 t0 = __ldcs(&targ4[i0]);
        float4 t1 = __ldcs(&targ4[i1]);
        float4 w0 = __ldcs(&lw4[i0]);
        float4 w1 = __ldcs(&lw4[i1]);
        ghm_accum_vec4(p0, t0, w0, hist_col);
        ghm_accum_vec4(p1, t1, w1, hist_col);
    }

    // Ragged remainder (< 2T float4s): checked grid-stride, still coalesced.
    for (long long i = nmain + gid; i < nvec; i += T) {
        float4 p = __ldcs(&pred4[i]);
        float4 t = __ldcs(&targ4[i]);
        float4 w = __ldcs(&lw4[i]);
        ghm_accum_vec4(p, t, w, hist_col);
    }

    // Scalar tail (ntotal not divisible by 4) — first threads of block 0.
    long long tail_base = nvec * 4;
    long long rem = ntotal - tail_base;
    if (blockIdx.x == 0 && (long long)tid < rem) {
        long long j = tail_base + tid;
        ghm_accum_elem(__ldcs(&pred[j]), __ldcs(&targ[j]), __ldcs(&lw[j]), hist_col);
    }

    __syncthreads();

    // Block tree reduction over the thread dimension for each bin.
    for (int off = GHM_BLOCK / 2; off > 0; off >>= 1) {
        if (tid < off) {
#pragma unroll
            for (int b = 0; b < GHM_BINS; b++) {
                float2 a = hist[b][tid];
                float2 c = hist[b][tid + off];
                hist[b][tid] = make_float2(a.x + c.x, a.y + c.y);
            }
        }
        __syncthreads();
    }

    if (tid < GHM_BINS) {
        atomicAdd(&g_ghm_counts[tid], hist[tid][0].x);
        atomicAdd(&g_ghm_sums[tid],   hist[tid][0].y);
    }

    // Last-block finalize (threadFenceReduction pattern).
    __threadfence();
    if (tid == 0) {
        unsigned int t = atomicAdd(&g_ghm_ticket, 1u);
        s_is_last = (t == gridDim.x - 1);
    }
    __syncthreads();

    if (s_is_last && tid == 0) {
        // loss = (sum over nonempty bins of S_b / count_b) / max(n, 1);
        // tot cancels between w_per_bin = tot/count and the final /tot.
        float n = 0.0f;
        float acc = 0.0f;
#pragma unroll
        for (int b = 0; b < GHM_BINS; b++) {
            float c = g_ghm_counts[b];
            if (c > 0.0f) {
                n += 1.0f;
                acc += g_ghm_sums[b] / c;
            }
        }
        out[0] = acc / fmaxf(n, 1.0f);

        // Reset globals for the next (graph-replayed) launch.
#pragma unroll
        for (int b = 0; b < GHM_BINS; b++) {
            g_ghm_counts[b] = 0.0f;
            g_ghm_sums[b]   = 0.0f;
        }
        __threadfence();
        g_ghm_ticket = 0u;
    }
}

extern "C" void kernel_launch(void* const* d_in, const int* in_sizes, int n_in,
                              void* d_out, int out_size) {
    const float* pred = (const float*)d_in[0];
    const float* targ = (const float*)d_in[1];
    const float* lw   = (const float*)d_in[2];
    float* out = (float*)d_out;

    long long ntotal = (long long)in_sizes[0];
    long long nvec = ntotal / 4;

    ghm_main_kernel<<<GHM_GRID, GHM_BLOCK>>>(
        (const float4*)pred, (const float4*)targ, (const float4*)lw,
        pred, targ, lw, nvec, ntotal, out);
    (void)n_in; (void)out_size;
}

// round 5
// speedup vs baseline: 1.2092x; 1.1020x over previous
#include <cuda_runtime.h>

#define GHM_BINS 10
#define GHM_BLOCK 256
// oe=4 CTAs/SM: keeps oe*MLP_p1 = 12 below the L1tex cross-CTA contention
// threshold (~16) while 32 warps/SM x 1.5KB in-flight covers BW*latency.
#define GHM_GRID (148 * 4)

// Global accumulators (allocation-free scratch). Zero at module load; the
// last block resets them after finalizing, so every launch starts clean.
__device__ float g_ghm_counts[GHM_BINS];
__device__ float g_ghm_sums[GHM_BINS];
__device__ unsigned int g_ghm_ticket;

__device__ __forceinline__ void ghm_accum_elem(float p, float t, float w,
                                               float2* hist_col /* &hist[0][tid], stride GHM_BLOCK */) {
    // e = exp(-|p|)
    float ap = fabsf(p);
    float e  = __expf(-ap);              // MUFU.EX2 path
    float d  = 1.0f + e;
    float lp = __logf(d);                // log1p(exp(-|p|)); MUFU.LG2
    // stable BCE-with-logits
    float bce = fmaxf(p, 0.0f) - p * t + lp;
    // sigmoid(p) from same e: p>=0 -> 1/(1+e), else e/(1+e) = 1 - 1/(1+e)
    float u = __fdividef(1.0f, d);       // MUFU.RCP
    float s = (p >= 0.0f) ? u : (1.0f - u);
    float g10 = fabsf(s - t) * 10.0f;    // g in [0,1] -> g10 in [0,10]
    int idx = (int)g10;                  // floor (g10 >= 0)
    idx = min(idx, GHM_BINS - 1);        // clip top edge
    float vf = (w > 0.0f) ? 1.0f : 0.0f;
    float2 h = hist_col[idx * GHM_BLOCK];
    h.x += vf;
    h.y = fmaf(vf, bce, h.y);
    hist_col[idx * GHM_BLOCK] = h;
}

__global__ __launch_bounds__(GHM_BLOCK)
void ghm_main_kernel(const float4* __restrict__ pred4,
                     const float4* __restrict__ targ4,
                     const float4* __restrict__ lw4,
                     const float* __restrict__ pred,
                     const float* __restrict__ targ,
                     const float* __restrict__ lw,
                     long long nvec, long long ntotal,
                     float* __restrict__ out) {
    // Thread-private histogram stripes: hist[bin][tid] as {count, bce_sum}.
    // Address = (bin*GHM_BLOCK + tid)*8 bytes -> conflict-free LDS.64/STS.64.
    __shared__ float2 hist[GHM_BINS][GHM_BLOCK];
    __shared__ bool s_is_last;

    const int tid = threadIdx.x;
#pragma unroll
    for (int b = 0; b < GHM_BINS; b++) hist[b][tid] = make_float2(0.0f, 0.0f);
    __syncthreads();

    float2* hist_col = &hist[0][tid];

    long long stride = (long long)gridDim.x * (long long)blockDim.x;
    for (long long i = (long long)blockIdx.x * blockDim.x + tid; i < nvec; i += stride) {
        // Streaming loads: zero reuse, keep L2 evict-first. MLP_p1 = 3.
        float4 p = __ldcs(&pred4[i]);
        float4 t = __ldcs(&targ4[i]);
        float4 w = __ldcs(&lw4[i]);
        ghm_accum_elem(p.x, t.x, w.x, hist_col);
        ghm_accum_elem(p.y, t.y, w.y, hist_col);
        ghm_accum_elem(p.z, t.z, w.z, hist_col);
        ghm_accum_elem(p.w, t.w, w.w, hist_col);
    }

    // Scalar tail (ntotal not divisible by 4) — first threads of block 0.
    long long tail_base = nvec * 4;
    long long rem = ntotal - tail_base;
    if (blockIdx.x == 0 && (long long)tid < rem) {
        long long j = tail_base + tid;
        ghm_accum_elem(__ldcs(&pred[j]), __ldcs(&targ[j]), __ldcs(&lw[j]), hist_col);
    }

    __syncthreads();

    // Block tree reduction over the thread dimension for each bin.
    for (int off = GHM_BLOCK / 2; off > 0; off >>= 1) {
        if (tid < off) {
#pragma unroll
            for (int b = 0; b < GHM_BINS; b++) {
                float2 a = hist[b][tid];
                float2 c = hist[b][tid + off];
                hist[b][tid] = make_float2(a.x + c.x, a.y + c.y);
            }
        }
        __syncthreads();
    }

    if (tid < GHM_BINS) {
        atomicAdd(&g_ghm_counts[tid], hist[tid][0].x);
        atomicAdd(&g_ghm_sums[tid],   hist[tid][0].y);
    }

    // Last-block finalize (threadFenceReduction pattern).
    __threadfence();
    if (tid == 0) {
        unsigned int t = atomicAdd(&g_ghm_ticket, 1u);
        s_is_last = (t == gridDim.x - 1);
    }
    __syncthreads();

    if (s_is_last && tid == 0) {
        // loss = (sum over nonempty bins of S_b / count_b) / max(n, 1);
        // tot cancels between w_per_bin = tot/count and the final /tot.
        float n = 0.0f;
        float acc = 0.0f;
#pragma unroll
        for (int b = 0; b < GHM_BINS; b++) {
            float c = g_ghm_counts[b];
            if (c > 0.0f) {
                n += 1.0f;
                acc += g_ghm_sums[b] / c;
            }
        }
        out[0] = acc / fmaxf(n, 1.0f);

        // Reset globals for the next (graph-replayed) launch.
#pragma unroll
        for (int b = 0; b < GHM_BINS; b++) {
            g_ghm_counts[b] = 0.0f;
            g_ghm_sums[b]   = 0.0f;
        }
        __threadfence();
        g_ghm_ticket = 0u;
    }
}

extern "C" void kernel_launch(void* const* d_in, const int* in_sizes, int n_in,
                              void* d_out, int out_size) {
    const float* pred = (const float*)d_in[0];
    const float* targ = (const float*)d_in[1];
    const float* lw   = (const float*)d_in[2];
    float* out = (float*)d_out;

    long long ntotal = (long long)in_sizes[0];
    long long nvec = ntotal / 4;

    ghm_main_kernel<<<GHM_GRID, GHM_BLOCK>>>(
        (const float4*)pred, (const float4*)targ, (const float4*)lw,
        pred, targ, lw, nvec, ntotal, out);
    (void)n_in; (void)out_size;
}